// round 1
// baseline (speedup 1.0000x reference)
#include <cuda_runtime.h>
#include <cstdint>
#include <math.h>

// ---------------- problem constants ----------------
#define NGEN 10
#define BSZ  4096
#define INDIM 512
#define DIM  1024
#define MAX_TILES 48   // sum ceil(cnt_g/128) <= 4096/128 + 10 = 42

// ---------------- scratch (device globals; no runtime alloc) ----------------
__device__ float g_x [BSZ * INDIM];   // reparam sample
__device__ float g_s1[BSZ * DIM];     // shared layer 1 out / expert h (reused)
__device__ float g_s2[BSZ * DIM];     // shared layer 2 out
__device__ int   g_perm[BSZ];         // sorted pos -> original row
__device__ int   g_tile_genre[MAX_TILES];
__device__ int   g_tile_start[MAX_TILES];
__device__ int   g_tile_rows [MAX_TILES];
__device__ int   g_tile_count;

// ---------------- helpers ----------------
__device__ __forceinline__ unsigned f2tf(float x) {
    unsigned r;
    asm("cvt.rna.tf32.f32 %0, %1;" : "=r"(r) : "f"(x));
    return r;
}
__device__ __forceinline__ float gelu_f(float x) {
    return 0.5f * x * (1.0f + erff(x * 0.70710678118654752f));
}

// ---------------- reparameterized sample: x = mu[g] + (|sigma[g]|+eps)*z ----
__global__ void noise_kernel(const float4* __restrict__ mu,
                             const float4* __restrict__ sig,
                             const float4* __restrict__ z,
                             const int* __restrict__ genre,
                             float4* __restrict__ x) {
    const int C4 = INDIM / 4;
    int i = blockIdx.x * blockDim.x + threadIdx.x;
    if (i >= BSZ * C4) return;
    int row = i / C4, c = i - row * C4;
    int g = genre[row];
    float4 m = mu[g * C4 + c];
    float4 s = sig[g * C4 + c];
    float4 zz = z[i];
    float4 o;
    o.x = m.x + (fabsf(s.x) + 1e-8f) * zz.x;
    o.y = m.y + (fabsf(s.y) + 1e-8f) * zz.y;
    o.z = m.z + (fabsf(s.z) + 1e-8f) * zz.z;
    o.w = m.w + (fabsf(s.w) + 1e-8f) * zz.w;
    x[i] = o;
}

// ---------------- grouping: stable sort rows by genre + tile map ------------
__global__ void group_kernel(const int* __restrict__ genre) {
    __shared__ int cnt[256 * NGEN];
    __shared__ int tot[NGEN];
    __shared__ int base[NGEN];
    int t = threadIdx.x;
    const int per = BSZ / 256;   // 16

    int lc[NGEN];
#pragma unroll
    for (int g = 0; g < NGEN; g++) lc[g] = 0;
    int gr[per];
    for (int i = 0; i < per; i++) {
        int g = genre[t * per + i];
        gr[i] = g;
        lc[g]++;
    }
    for (int g = 0; g < NGEN; g++) cnt[t * NGEN + g] = lc[g];
    __syncthreads();

    if (t < NGEN) {   // exclusive scan over threads, per genre
        int s = 0;
        for (int tt = 0; tt < 256; tt++) {
            int v = cnt[tt * NGEN + t];
            cnt[tt * NGEN + t] = s;
            s += v;
        }
        tot[t] = s;
    }
    __syncthreads();

    if (t == 0) {
        int off = 0;
        for (int g = 0; g < NGEN; g++) { base[g] = off; off += tot[g]; }
        int T = 0;
        for (int g = 0; g < NGEN; g++) {
            int c = tot[g], s0 = base[g];
            while (c > 0) {
                g_tile_genre[T] = g;
                g_tile_start[T] = s0;
                g_tile_rows[T]  = c < 128 ? c : 128;
                s0 += 128; c -= 128; T++;
            }
        }
        g_tile_count = T;
    }
    __syncthreads();

    int run[NGEN];
#pragma unroll
    for (int g = 0; g < NGEN; g++) run[g] = cnt[t * NGEN + g];
    for (int i = 0; i < per; i++) {
        int g = gr[i];
        int pos = base[g] + run[g]++;
        g_perm[pos] = t * per + i;
    }
}

// ---------------- TF32 tiled GEMM (bias + optional GELU epilogue) -----------
// C[M,N] = act( A[M,K] @ B[K,N] + bias ), optional row gather (A) / scatter (C)
constexpr int BM = 128, BN = 128, BK = 32, TPB = 256;
constexpr int SA = 36, SB = 132;                 // padded smem strides (words)
constexpr int AS_ELE = BM * SA;                  // 4608
constexpr int BS_ELE = BK * SB;                  // 4224
constexpr int SMEM_BYTES = 2 * (AS_ELE + BS_ELE) * 4;  // 70656

template<bool EXPERT, bool GATHER_A, bool SCATTER_C, bool GELU>
__global__ void __launch_bounds__(TPB)
gemm_tf32(const float* __restrict__ A, const float* __restrict__ Bw,
          const float* __restrict__ bias, float* __restrict__ C,
          int M, int N, int K,
          const int* __restrict__ perm,
          const int* __restrict__ tgen, const int* __restrict__ tstart,
          const int* __restrict__ trows, const int* __restrict__ tcnt)
{
    extern __shared__ float smem[];
    unsigned* Asu = (unsigned*)smem;                    // 2 stages A
    unsigned* Bsu = (unsigned*)(smem) + 2 * AS_ELE;     // 2 stages B

    int m0, rows, genre = 0;
    if (EXPERT) {
        if ((int)blockIdx.x >= *tcnt) return;
        genre = tgen[blockIdx.x];
        m0    = tstart[blockIdx.x];
        rows  = trows[blockIdx.x];
    } else {
        m0 = blockIdx.x * BM;
        rows = M - m0; if (rows > BM) rows = BM;
    }
    const int n0 = blockIdx.y * BN;
    const float* Bsel = EXPERT ? Bw + (size_t)genre * K * N : Bw;
    const float* bsel = EXPERT ? bias + genre * N : bias;

    const int tid = threadIdx.x;

    // --- global loaders ---
    const int a_r = tid >> 3;           // 0..31 (4 passes of 32 rows)
    const int a_c = (tid & 7) * 4;      // 0..28
    const float* aptr[4];
#pragma unroll
    for (int p = 0; p < 4; p++) {
        int lr = a_r + 32 * p;
        int lrc = lr < rows ? lr : (rows - 1);
        int src = m0 + lrc;
        if (GATHER_A) src = perm[src];
        aptr[p] = A + (size_t)src * K + a_c;
    }
    const int b_r = tid >> 5;           // 0..7 (4 passes of 8 rows)
    const int b_c = (tid & 31) * 4;
    const float* bptr = Bsel + (size_t)b_r * N + n0 + b_c;

    // --- prologue: load tile 0 ---
#pragma unroll
    for (int p = 0; p < 4; p++) {
        float4 v = *(const float4*)(aptr[p]);
        uint4 u = make_uint4(f2tf(v.x), f2tf(v.y), f2tf(v.z), f2tf(v.w));
        *(uint4*)(Asu + (a_r + 32 * p) * SA + a_c) = u;
    }
#pragma unroll
    for (int p = 0; p < 4; p++) {
        float4 v = *(const float4*)(bptr + (size_t)(8 * p) * N);
        uint4 u = make_uint4(f2tf(v.x), f2tf(v.y), f2tf(v.z), f2tf(v.w));
        *(uint4*)(Bsu + (b_r + 8 * p) * SB + b_c) = u;
    }
    __syncthreads();

    const int lane = tid & 31, wid = tid >> 5;
    const int wm = (wid >> 2) * 64;     // warp m offset (0 / 64)
    const int wn = (wid & 3) * 32;      // warp n offset (0..96)
    const int grp = lane >> 2, qid = lane & 3;

    float acc[4][4][4];
#pragma unroll
    for (int i = 0; i < 4; i++)
#pragma unroll
        for (int j = 0; j < 4; j++)
#pragma unroll
            for (int q = 0; q < 4; q++) acc[i][j][q] = 0.f;

    const int nk = K / BK;
    int cur = 0;
    for (int kt = 0; kt < nk; kt++) {
        float4 av[4], bv[4];
        const bool pf = (kt + 1 < nk);
        if (pf) {
            int k0n = (kt + 1) * BK;
#pragma unroll
            for (int p = 0; p < 4; p++) av[p] = *(const float4*)(aptr[p] + k0n);
#pragma unroll
            for (int p = 0; p < 4; p++) bv[p] = *(const float4*)(bptr + (size_t)(k0n + 8 * p) * N);
        }
        const unsigned* Au = Asu + cur * AS_ELE;
        const unsigned* Bu = Bsu + cur * BS_ELE;
#pragma unroll
        for (int ks = 0; ks < 4; ks++) {
            unsigned af[4][4], bf[4][2];
#pragma unroll
            for (int mt = 0; mt < 4; mt++) {
                int r = wm + mt * 16 + grp;
                int c = ks * 8 + qid;
                af[mt][0] = Au[r * SA + c];
                af[mt][1] = Au[(r + 8) * SA + c];
                af[mt][2] = Au[r * SA + c + 4];
                af[mt][3] = Au[(r + 8) * SA + c + 4];
            }
#pragma unroll
            for (int nt = 0; nt < 4; nt++) {
                int k = ks * 8 + qid;
                int n = wn + nt * 8 + grp;
                bf[nt][0] = Bu[k * SB + n];
                bf[nt][1] = Bu[(k + 4) * SB + n];
            }
#pragma unroll
            for (int mt = 0; mt < 4; mt++)
#pragma unroll
                for (int nt = 0; nt < 4; nt++) {
                    float* d = acc[mt][nt];
                    asm volatile(
                        "mma.sync.aligned.m16n8k8.row.col.f32.tf32.tf32.f32 "
                        "{%0,%1,%2,%3},{%4,%5,%6,%7},{%8,%9},{%0,%1,%2,%3};\n"
                        : "+f"(d[0]), "+f"(d[1]), "+f"(d[2]), "+f"(d[3])
                        : "r"(af[mt][0]), "r"(af[mt][1]), "r"(af[mt][2]), "r"(af[mt][3]),
                          "r"(bf[nt][0]), "r"(bf[nt][1]));
                }
        }
        if (pf) {
            int nxt = cur ^ 1;
            unsigned* Ad = Asu + nxt * AS_ELE;
            unsigned* Bd = Bsu + nxt * BS_ELE;
#pragma unroll
            for (int p = 0; p < 4; p++) {
                uint4 u = make_uint4(f2tf(av[p].x), f2tf(av[p].y), f2tf(av[p].z), f2tf(av[p].w));
                *(uint4*)(Ad + (a_r + 32 * p) * SA + a_c) = u;
            }
#pragma unroll
            for (int p = 0; p < 4; p++) {
                uint4 u = make_uint4(f2tf(bv[p].x), f2tf(bv[p].y), f2tf(bv[p].z), f2tf(bv[p].w));
                *(uint4*)(Bd + (b_r + 8 * p) * SB + b_c) = u;
            }
            cur = nxt;
        }
        __syncthreads();
    }

    // --- epilogue: bias (+GELU), gather/scatter rows ---
#pragma unroll
    for (int mt = 0; mt < 4; mt++) {
#pragma unroll
        for (int h = 0; h < 2; h++) {
            int rl = wm + mt * 16 + grp + 8 * h;
            if (rl < rows) {
                int orow = m0 + rl;
                if (SCATTER_C) orow = perm[orow];
                float* crow = C + (size_t)orow * N + n0 + wn;
#pragma unroll
                for (int nt = 0; nt < 4; nt++) {
                    int c = nt * 8 + 2 * qid;
                    float x0 = acc[mt][nt][2 * h + 0] + bsel[n0 + wn + c];
                    float x1 = acc[mt][nt][2 * h + 1] + bsel[n0 + wn + c + 1];
                    if (GELU) { x0 = gelu_f(x0); x1 = gelu_f(x1); }
                    *(float2*)(crow + c) = make_float2(x0, x1);
                }
            }
        }
    }
}

// ---------------- launcher ----------------
extern "C" void kernel_launch(void* const* d_in, const int* in_sizes, int n_in,
                              void* d_out, int out_size) {
    const int*   genre = (const int*)  d_in[1];
    const float* z     = (const float*)d_in[2];
    const float* mu    = (const float*)d_in[3];
    const float* sigma = (const float*)d_in[4];
    const float* Ws1   = (const float*)d_in[5];
    const float* bs1   = (const float*)d_in[6];
    const float* Ws2   = (const float*)d_in[7];
    const float* bs2   = (const float*)d_in[8];
    const float* We1   = (const float*)d_in[9];
    const float* be1   = (const float*)d_in[10];
    const float* We2   = (const float*)d_in[11];
    const float* be2   = (const float*)d_in[12];
    float* out = (float*)d_out;

    void *px, *ps1, *ps2, *pperm, *ptg, *pts, *ptr_, *ptc;
    cudaGetSymbolAddress(&px,   g_x);
    cudaGetSymbolAddress(&ps1,  g_s1);
    cudaGetSymbolAddress(&ps2,  g_s2);
    cudaGetSymbolAddress(&pperm, g_perm);
    cudaGetSymbolAddress(&ptg,  g_tile_genre);
    cudaGetSymbolAddress(&pts,  g_tile_start);
    cudaGetSymbolAddress(&ptr_, g_tile_rows);
    cudaGetSymbolAddress(&ptc,  g_tile_count);
    float* x  = (float*)px;
    float* s1 = (float*)ps1;
    float* s2 = (float*)ps2;
    const int* perm = (const int*)pperm;
    const int* tg = (const int*)ptg;
    const int* ts = (const int*)pts;
    const int* tr = (const int*)ptr_;
    const int* tc = (const int*)ptc;

    cudaFuncSetAttribute(gemm_tf32<false,false,false,true>,
                         cudaFuncAttributeMaxDynamicSharedMemorySize, SMEM_BYTES);
    cudaFuncSetAttribute(gemm_tf32<true,true,false,true>,
                         cudaFuncAttributeMaxDynamicSharedMemorySize, SMEM_BYTES);
    cudaFuncSetAttribute(gemm_tf32<true,false,true,false>,
                         cudaFuncAttributeMaxDynamicSharedMemorySize, SMEM_BYTES);

    // 1) reparameterized sample
    {
        int total = BSZ * INDIM / 4;
        noise_kernel<<<(total + 255) / 256, 256>>>(
            (const float4*)mu, (const float4*)sigma, (const float4*)z, genre, (float4*)x);
    }
    // 2) grouping (perm + tile map)
    group_kernel<<<1, 256>>>(genre);

    // 3) shared MLP
    dim3 gs(BSZ / BM, DIM / BN);
    gemm_tf32<false,false,false,true><<<gs, TPB, SMEM_BYTES>>>(
        x, Ws1, bs1, s1, BSZ, DIM, INDIM, nullptr, nullptr, nullptr, nullptr, nullptr);
    gemm_tf32<false,false,false,true><<<gs, TPB, SMEM_BYTES>>>(
        s1, Ws2, bs2, s2, BSZ, DIM, DIM, nullptr, nullptr, nullptr, nullptr, nullptr);

    // 4) expert layers (grouped by genre; gather rows in, scatter rows out)
    dim3 ge(MAX_TILES, DIM / BN);
    gemm_tf32<true,true,false,true><<<ge, TPB, SMEM_BYTES>>>(
        s2, We1, be1, s1, BSZ, DIM, DIM, perm, tg, ts, tr, tc);
    gemm_tf32<true,false,true,false><<<ge, TPB, SMEM_BYTES>>>(
        s1, We2, be2, out, BSZ, DIM, DIM, perm, tg, ts, tr, tc);
}